// round 5
// baseline (speedup 1.0000x reference)
#include <cuda_runtime.h>
#include <cuda_bf16.h>
#include <math.h>
#include <stdint.h>

// Problem constants
#define S_LEN 2048
#define DIM   1536
#define NH    12
#define HD    128
#define CHALF (HD/2)
#define SEG0  22
#define SEG1  21

// ---------------- scratch (device globals) ----------------------------------
__device__ float g_q[S_LEN * DIM];
__device__ float g_k[S_LEN * DIM];

__device__ uint4 g_qh[S_LEN * DIM / 8];     // x split -> Q split (after norm)
__device__ uint4 g_ql[S_LEN * DIM / 8];
__device__ uint4 g_wh[3 * DIM * DIM / 8];   // wq|wk|wv split
__device__ uint4 g_wl[3 * DIM * DIM / 8];
__device__ uint4 g_oh[DIM * DIM / 8];       // wo split
__device__ uint4 g_ol[DIM * DIM / 8];
__device__ uint4 g_kh[S_LEN * DIM / 8];     // K split
__device__ uint4 g_kl[S_LEN * DIM / 8];
__device__ uint4 g_vh[S_LEN * DIM / 8];     // V split (written by gemm epilogue)
__device__ uint4 g_vl[S_LEN * DIM / 8];
__device__ uint4 g_aoh[S_LEN * DIM / 8];    // attention output split
__device__ uint4 g_aol[S_LEN * DIM / 8];
__device__ uint4 g_xh[S_LEN * DIM / 8];     // x split
__device__ uint4 g_xl[S_LEN * DIM / 8];

// ---------------- PTX helpers ------------------------------------------------
__device__ __forceinline__ uint32_t smem_u32(const void* p) {
    uint32_t a;
    asm("{ .reg .u64 t; cvta.to.shared.u64 t, %1; cvt.u32.u64 %0, t; }" : "=r"(a) : "l"(p));
    return a;
}
__device__ __forceinline__ void ldsm_x4(uint32_t* r, uint32_t addr) {
    asm volatile("ldmatrix.sync.aligned.m8n8.x4.shared.b16 {%0,%1,%2,%3}, [%4];"
        : "=r"(r[0]), "=r"(r[1]), "=r"(r[2]), "=r"(r[3]) : "r"(addr));
}
__device__ __forceinline__ void ldsm_x4_t(uint32_t* r, uint32_t addr) {
    asm volatile("ldmatrix.sync.aligned.m8n8.x4.trans.shared.b16 {%0,%1,%2,%3}, [%4];"
        : "=r"(r[0]), "=r"(r[1]), "=r"(r[2]), "=r"(r[3]) : "r"(addr));
}
__device__ __forceinline__ void mma_bf16(float* c, const uint32_t* a, const uint32_t* b) {
    asm volatile(
        "mma.sync.aligned.m16n8k16.row.col.f32.bf16.bf16.f32 "
        "{%0,%1,%2,%3}, {%4,%5,%6,%7}, {%8,%9}, {%0,%1,%2,%3};"
        : "+f"(c[0]), "+f"(c[1]), "+f"(c[2]), "+f"(c[3])
        : "r"(a[0]), "r"(a[1]), "r"(a[2]), "r"(a[3]), "r"(b[0]), "r"(b[1]));
}
__device__ __forceinline__ void cp16(uint32_t dst, const void* src) {
    asm volatile("cp.async.cg.shared.global [%0], [%1], 16;" :: "r"(dst), "l"(src));
}
#define CP_COMMIT()  asm volatile("cp.async.commit_group;" ::: "memory")
#define CP_WAIT(n)   asm volatile("cp.async.wait_group %0;" :: "n"(n) : "memory")

// split helpers
__device__ __forceinline__ void split2(float v0, float v1, uint32_t& h, uint32_t& l) {
    __nv_bfloat16 h0 = __float2bfloat16_rn(v0);
    __nv_bfloat16 h1 = __float2bfloat16_rn(v1);
    __nv_bfloat16 l0 = __float2bfloat16_rn(v0 - __bfloat162float(h0));
    __nv_bfloat16 l1 = __float2bfloat16_rn(v1 - __bfloat162float(h1));
    h = (uint32_t)__bfloat16_as_ushort(h0) | ((uint32_t)__bfloat16_as_ushort(h1) << 16);
    l = (uint32_t)__bfloat16_as_ushort(l0) | ((uint32_t)__bfloat16_as_ushort(l1) << 16);
}

// ---------------- fp32 -> bf16 hi/lo split ------------------------------------
__global__ __launch_bounds__(256)
void conv_split(const float4* __restrict__ src, uint4* __restrict__ hi,
                uint4* __restrict__ lo, int n8)
{
    int idx = blockIdx.x * blockDim.x + threadIdx.x;
    if (idx >= n8) return;
    float4 a = src[2 * idx], b = src[2 * idx + 1];
    float xs[8] = {a.x, a.y, a.z, a.w, b.x, b.y, b.z, b.w};
    uint32_t h[4], l[4];
#pragma unroll
    for (int i = 0; i < 4; i++) split2(xs[2 * i], xs[2 * i + 1], h[i], l[i]);
    hi[idx] = make_uint4(h[0], h[1], h[2], h[3]);
    lo[idx] = make_uint4(l[0], l[1], l[2], l[3]);
}

// batched 3-weight split (wq|wk|wv) via blockIdx.y
__global__ __launch_bounds__(256)
void conv_split_w3(const float4* __restrict__ w0, const float4* __restrict__ w1,
                   const float4* __restrict__ w2, uint4* __restrict__ hi,
                   uint4* __restrict__ lo, int n8)
{
    int idx = blockIdx.x * blockDim.x + threadIdx.x;
    if (idx >= n8) return;
    const float4* src = (blockIdx.y == 0) ? w0 : (blockIdx.y == 1) ? w1 : w2;
    size_t off = (size_t)blockIdx.y * n8;
    float4 a = src[2 * idx], b = src[2 * idx + 1];
    float xs[8] = {a.x, a.y, a.z, a.w, b.x, b.y, b.z, b.w};
    uint32_t h[4], l[4];
#pragma unroll
    for (int i = 0; i < 4; i++) split2(xs[2 * i], xs[2 * i + 1], h[i], l[i]);
    hi[off + idx] = make_uint4(h[0], h[1], h[2], h[3]);
    lo[off + idx] = make_uint4(l[0], l[1], l[2], l[3]);
}

// ---------------- bf16-split GEMM via mma.sync --------------------------------
// For w==2 (V), writes bf16 split directly instead of fp32.
#define PITCH  80
#define TILEB  (128 * PITCH)
#define STAGEB (4 * TILEB)
#define GEMM_SMEM (2 * STAGEB)
#define NSTAGE 48

__global__ __launch_bounds__(256)
void gemm_mma(const uint4* __restrict__ Ah, const uint4* __restrict__ Al,
              const uint4* __restrict__ Wh, const uint4* __restrict__ Wl,
              const float* __restrict__ b0, const float* __restrict__ b1,
              const float* __restrict__ b2,
              float* __restrict__ C0, float* __restrict__ C1,
              uint32_t* __restrict__ Vh, uint32_t* __restrict__ Vl,
              int ntw)
{
    extern __shared__ char smc[];
    const uint32_t sb = smem_u32(smc);
    const int tid  = threadIdx.x;
    const int wid  = tid >> 5;
    const int lane = tid & 31;
    const int warp_m = wid & 1;
    const int warp_n = wid >> 1;

    const int m0     = blockIdx.x * 128;
    const int ntile  = blockIdx.y;
    const int w      = ntile / ntw;
    const int ncol0  = (ntile % ntw) * 128;
    const size_t wrow0 = (size_t)ntile * 128;

    const int lr = tid >> 2;
    const int lj = tid & 3;

    float acc[4][4][4];
#pragma unroll
    for (int i = 0; i < 4; i++)
#pragma unroll
        for (int j = 0; j < 4; j++)
#pragma unroll
            for (int k = 0; k < 4; k++) acc[i][j][k] = 0.f;

    auto prefetch = [&](int c, int buf) {
        const uint32_t st = sb + buf * STAGEB;
        const int kc4 = c * 4;
#pragma unroll
        for (int i = 0; i < 2; i++) {
            int r = lr + i * 64;
            uint32_t so = (uint32_t)(r * PITCH + lj * 16);
            size_t ga = (size_t)(m0 + r) * (DIM / 8) + kc4 + lj;
            cp16(st + 0 * TILEB + so, Ah + ga);
            cp16(st + 1 * TILEB + so, Al + ga);
            size_t gb = (wrow0 + r) * (DIM / 8) + kc4 + lj;
            cp16(st + 2 * TILEB + so, Wh + gb);
            cp16(st + 3 * TILEB + so, Wl + gb);
        }
        CP_COMMIT();
    };

    prefetch(0, 0);
    prefetch(1, 1);

    const uint32_t a_lo = (uint32_t)((warp_m * 64 + (lane & 15)) * PITCH + (lane >> 4) * 16);
    const uint32_t b_lo = (uint32_t)((warp_n * 32 + (lane & 7) + ((lane >> 4) << 3)) * PITCH
                                     + ((lane >> 3) & 1) * 16);

    for (int c = 0; c < NSTAGE; c++) {
        if (c < NSTAGE - 1) { CP_WAIT(1); } else { CP_WAIT(0); }
        __syncthreads();

        const uint32_t st = sb + (c & 1) * STAGEB;
#pragma unroll
        for (int ks = 0; ks < 2; ks++) {
            uint32_t ah[4][4], al[4][4], bh[2][4], bl[2][4];
#pragma unroll
            for (int mt = 0; mt < 4; mt++) {
                uint32_t base = st + mt * (16 * PITCH) + ks * 32 + a_lo;
                ldsm_x4(ah[mt], base);
                ldsm_x4(al[mt], base + TILEB);
            }
#pragma unroll
            for (int np = 0; np < 2; np++) {
                uint32_t base = st + 2 * TILEB + np * (16 * PITCH) + ks * 32 + b_lo;
                ldsm_x4(bh[np], base);
                ldsm_x4(bl[np], base + TILEB);
            }
#pragma unroll
            for (int mt = 0; mt < 4; mt++) {
#pragma unroll
                for (int nt = 0; nt < 4; nt++) {
                    const uint32_t* bhp = &bh[nt >> 1][(nt & 1) * 2];
                    const uint32_t* blp = &bl[nt >> 1][(nt & 1) * 2];
                    mma_bf16(acc[mt][nt], ah[mt], bhp);
                    mma_bf16(acc[mt][nt], ah[mt], blp);
                    mma_bf16(acc[mt][nt], al[mt], bhp);
                }
            }
        }
        __syncthreads();
        if (c + 2 < NSTAGE) prefetch(c + 2, c & 1);
    }

    const float* bias = (w == 0) ? b0 : (w == 1) ? b1 : b2;
    const int g = lane >> 2, t4 = lane & 3;

    if (w < 2) {
        float* C = (w == 0) ? C0 : C1;
#pragma unroll
        for (int mt = 0; mt < 4; mt++) {
            int row = m0 + warp_m * 64 + mt * 16 + g;
#pragma unroll
            for (int nt = 0; nt < 4; nt++) {
                int col = ncol0 + warp_n * 32 + nt * 8 + t4 * 2;
                float2 bv = *(const float2*)(bias + col);
                float2 o0, o1;
                o0.x = acc[mt][nt][0] + bv.x;  o0.y = acc[mt][nt][1] + bv.y;
                o1.x = acc[mt][nt][2] + bv.x;  o1.y = acc[mt][nt][3] + bv.y;
                *(float2*)(C + (size_t)row * DIM + col)       = o0;
                *(float2*)(C + (size_t)(row + 8) * DIM + col) = o1;
            }
        }
    } else {
        // V: write bf16 hi/lo split directly
#pragma unroll
        for (int mt = 0; mt < 4; mt++) {
            int row = m0 + warp_m * 64 + mt * 16 + g;
#pragma unroll
            for (int nt = 0; nt < 4; nt++) {
                int col = ncol0 + warp_n * 32 + nt * 8 + t4 * 2;
                float2 bv = *(const float2*)(bias + col);
                uint32_t h0, l0, h1, l1;
                split2(acc[mt][nt][0] + bv.x, acc[mt][nt][1] + bv.y, h0, l0);
                split2(acc[mt][nt][2] + bv.x, acc[mt][nt][3] + bv.y, h1, l1);
                size_t i0 = ((size_t)row * DIM + col) >> 1;
                size_t i1 = ((size_t)(row + 8) * DIM + col) >> 1;
                Vh[i0] = h0; Vl[i0] = l0;
                Vh[i1] = h1; Vl[i1] = l1;
            }
        }
    }
}

// ---------------- fused RMSNorm + RoPE -> bf16 splits -------------------------
__global__ __launch_bounds__(256)
void norm_rope_split(const float* __restrict__ Q, const float* __restrict__ K,
                     const float* __restrict__ gq, const float* __restrict__ gk,
                     const float* __restrict__ freqs, const int* __restrict__ grid_sizes,
                     uint32_t* __restrict__ Qh, uint32_t* __restrict__ Ql,
                     uint32_t* __restrict__ Kh, uint32_t* __restrict__ Kl,
                     float qscale)
{
    const int s   = blockIdx.x;
    const int tid = threadIdx.x;
    __shared__ float red[256];
    __shared__ float s_rq, s_rk;

    const float* qrow = Q + (size_t)s * DIM;
    const float* krow = K + (size_t)s * DIM;

    float sq = 0.f, sk = 0.f;
    for (int i = tid; i < DIM; i += 256) {
        float a = qrow[i]; sq += a * a;
        float b = krow[i]; sk += b * b;
    }
    red[tid] = sq; __syncthreads();
    for (int off = 128; off > 0; off >>= 1) {
        if (tid < off) red[tid] += red[tid + off];
        __syncthreads();
    }
    if (tid == 0) s_rq = rsqrtf(red[0] * (1.f / DIM) + 1e-6f);
    __syncthreads();
    red[tid] = sk; __syncthreads();
    for (int off = 128; off > 0; off >>= 1) {
        if (tid < off) red[tid] += red[tid + off];
        __syncthreads();
    }
    if (tid == 0) s_rk = rsqrtf(red[0] * (1.f / DIM) + 1e-6f);
    __syncthreads();

    const float rq = s_rq, rk = s_rk;

    const int hdim = grid_sizes[1];
    const int wdim = grid_sizes[2];
    const int wi = s % wdim;
    const int hi = (s / wdim) % hdim;
    const int fi = s / (wdim * hdim);

    for (int p = tid; p < NH * CHALF; p += 256) {
        const int head = p >> 6;
        const int c    = p & 63;
        int pos = (c < SEG0) ? fi : ((c < SEG0 + SEG1) ? hi : wi);
        float ang = freqs[(size_t)pos * CHALF + c];
        float sn, cs;
        sincosf(ang, &sn, &cs);

        const int d0 = head * HD + 2 * c;
        float q0 = qrow[d0]     * rq * gq[d0];
        float q1 = qrow[d0 + 1] * rq * gq[d0 + 1];
        float qv0 = (q0 * cs - q1 * sn) * qscale;
        float qv1 = (q0 * sn + q1 * cs) * qscale;

        float k0 = krow[d0]     * rk * gk[d0];
        float k1 = krow[d0 + 1] * rk * gk[d0 + 1];
        float kv0 = k0 * cs - k1 * sn;
        float kv1 = k0 * sn + k1 * cs;

        size_t i32 = ((size_t)s * DIM + d0) >> 1;
        uint32_t h, l;
        split2(qv0, qv1, h, l); Qh[i32] = h; Ql[i32] = l;
        split2(kv0, kv1, h, l); Kh[i32] = h; Kl[i32] = l;
    }
}

// ---------------- flash attention via mma.sync bf16-split --------------------
#define FQT    128
#define FKT    64
#define FPITCH 272
#define QH_OFF 0
#define QL_OFF (128 * FPITCH)
#define STG_OFF (2 * 128 * FPITCH)
#define KH_O   0
#define KL_O   (64 * FPITCH)
#define VH_O   (2 * 64 * FPITCH)
#define VL_O   (3 * 64 * FPITCH)
#define STG_SZ (4 * 64 * FPITCH)
#define FL_SMEM (STG_OFF + 2 * STG_SZ)

__global__ __launch_bounds__(256, 1)
void flash_mma(const uint4* __restrict__ Qh, const uint4* __restrict__ Ql,
               const uint4* __restrict__ Kh, const uint4* __restrict__ Kl,
               const uint4* __restrict__ Vh, const uint4* __restrict__ Vl,
               uint32_t* __restrict__ AOh, uint32_t* __restrict__ AOl,
               const int* __restrict__ seq_lens)
{
    extern __shared__ char smc[];
    const uint32_t sb = smem_u32(smc);
    const int tid  = threadIdx.x;
    const int wid  = tid >> 5;
    const int lane = tid & 31;
    const int g    = lane >> 2;
    const int t4   = lane & 3;
    const int head = blockIdx.y;
    const int q0   = blockIdx.x * FQT;
    const int seqlen = seq_lens[0];

    const int DIM8 = DIM / 8;
    const int h8   = head * (HD / 8);

#pragma unroll
    for (int i = 0; i < 8; i++) {
        int t = tid + 256 * i;
        int r = t >> 4, j = t & 15;
        uint32_t so = (uint32_t)(r * FPITCH + j * 16);
        size_t gi = (size_t)(q0 + r) * DIM8 + h8 + j;
        cp16(sb + QH_OFF + so, Qh + gi);
        cp16(sb + QL_OFF + so, Ql + gi);
    }
    CP_COMMIT();

    auto load_kv = [&](int kt, int buf) {
        uint32_t st = sb + STG_OFF + buf * STG_SZ;
        int kr0 = kt * FKT;
#pragma unroll
        for (int i = 0; i < 4; i++) {
            int t = tid + 256 * i;
            int r = t >> 4, j = t & 15;
            uint32_t so = (uint32_t)(r * FPITCH + j * 16);
            size_t gi = (size_t)(kr0 + r) * DIM8 + h8 + j;
            cp16(st + KH_O + so, Kh + gi);
            cp16(st + KL_O + so, Kl + gi);
            cp16(st + VH_O + so, Vh + gi);
            cp16(st + VL_O + so, Vl + gi);
        }
        CP_COMMIT();
    };

    load_kv(0, 0);
    load_kv(1, 1);

    float o[16][4];
#pragma unroll
    for (int i = 0; i < 16; i++)
#pragma unroll
        for (int j = 0; j < 4; j++) o[i][j] = 0.f;
    float m0 = -1e30f, m1 = -1e30f, l0 = 0.f, l1 = 0.f;

    const uint32_t a_off  = (uint32_t)((wid * 16 + (lane & 15)) * FPITCH + (lane >> 4) * 16);
    const uint32_t bk_off = (uint32_t)(((lane & 7) + ((lane >> 4) << 3)) * FPITCH
                                       + ((lane >> 3) & 1) * 16);
    const uint32_t bv_row = (uint32_t)((lane & 7) + (((lane >> 3) & 1) << 3));
    const uint32_t bv_col = (uint32_t)((lane >> 4) * 16);

    // preload Q fragments (hi+lo) into registers: Q is used for all 32 KV tiles
    CP_WAIT(2);
    __syncthreads();
    uint32_t qhf[8][4], qlf[8][4];
#pragma unroll
    for (int kk = 0; kk < 8; kk++) {
        ldsm_x4(qhf[kk], sb + QH_OFF + a_off + kk * 32);
        ldsm_x4(qlf[kk], sb + QL_OFF + a_off + kk * 32);
    }

    const int NT = S_LEN / FKT;
    for (int kt = 0; kt < NT; kt++) {
        if (kt < NT - 1) { CP_WAIT(1); } else { CP_WAIT(0); }
        __syncthreads();
        const uint32_t st = sb + STG_OFF + (kt & 1) * STG_SZ;

        // ---- scores ----
        float acc[8][4];
#pragma unroll
        for (int i = 0; i < 8; i++)
#pragma unroll
            for (int j = 0; j < 4; j++) acc[i][j] = 0.f;

#pragma unroll
        for (int kk = 0; kk < 8; kk++) {
#pragma unroll
            for (int np = 0; np < 4; np++) {
                uint32_t bh[4], bl[4];
                uint32_t kb = st + np * (16 * FPITCH) + bk_off + kk * 32;
                ldsm_x4(bh, kb + KH_O);
                ldsm_x4(bl, kb + KL_O);
                mma_bf16(acc[2*np],   qhf[kk], &bh[0]);
                mma_bf16(acc[2*np+1], qhf[kk], &bh[2]);
                mma_bf16(acc[2*np],   qhf[kk], &bl[0]);
                mma_bf16(acc[2*np+1], qhf[kk], &bl[2]);
                mma_bf16(acc[2*np],   qlf[kk], &bh[0]);
                mma_bf16(acc[2*np+1], qlf[kk], &bh[2]);
            }
        }

        // ---- mask + online softmax ----
        const int kr0 = kt * FKT;
        float mx0 = -1e30f, mx1 = -1e30f;
#pragma unroll
        for (int j = 0; j < 8; j++) {
            int c0 = kr0 + 8 * j + 2 * t4;
            if (c0 >= seqlen)     { acc[j][0] = -1e30f; acc[j][2] = -1e30f; }
            if (c0 + 1 >= seqlen) { acc[j][1] = -1e30f; acc[j][3] = -1e30f; }
            mx0 = fmaxf(mx0, fmaxf(acc[j][0], acc[j][1]));
            mx1 = fmaxf(mx1, fmaxf(acc[j][2], acc[j][3]));
        }
        mx0 = fmaxf(mx0, __shfl_xor_sync(0xffffffffu, mx0, 1));
        mx0 = fmaxf(mx0, __shfl_xor_sync(0xffffffffu, mx0, 2));
        mx1 = fmaxf(mx1, __shfl_xor_sync(0xffffffffu, mx1, 1));
        mx1 = fmaxf(mx1, __shfl_xor_sync(0xffffffffu, mx1, 2));

        float mn0 = fmaxf(m0, mx0), mn1 = fmaxf(m1, mx1);
        float al0 = __expf(m0 - mn0), al1 = __expf(m1 - mn1);
        m0 = mn0; m1 = mn1;

        float s0 = 0.f, s1 = 0.f;
        uint32_t ph0[8], ph1[8], pl0[8], pl1[8];
#pragma unroll
        for (int j = 0; j < 8; j++) {
            float p00 = __expf(acc[j][0] - mn0);
            float p01 = __expf(acc[j][1] - mn0);
            float p10 = __expf(acc[j][2] - mn1);
            float p11 = __expf(acc[j][3] - mn1);
            s0 += p00 + p01;
            s1 += p10 + p11;
            split2(p00, p01, ph0[j], pl0[j]);
            split2(p10, p11, ph1[j], pl1[j]);
        }
        s0 += __shfl_xor_sync(0xffffffffu, s0, 1);
        s0 += __shfl_xor_sync(0xffffffffu, s0, 2);
        s1 += __shfl_xor_sync(0xffffffffu, s1, 1);
        s1 += __shfl_xor_sync(0xffffffffu, s1, 2);
        l0 = l0 * al0 + s0;
        l1 = l1 * al1 + s1;

#pragma unroll
        for (int nt = 0; nt < 16; nt++) {
            o[nt][0] *= al0; o[nt][1] *= al0;
            o[nt][2] *= al1; o[nt][3] *= al1;
        }

        // ---- PV ----
#pragma unroll
        for (int k2 = 0; k2 < 4; k2++) {
            uint32_t aph[4] = { ph0[2*k2], ph1[2*k2], ph0[2*k2+1], ph1[2*k2+1] };
            uint32_t apl[4] = { pl0[2*k2], pl1[2*k2], pl0[2*k2+1], pl1[2*k2+1] };
            uint32_t vrow = st + (uint32_t)((k2 * 16 + bv_row) * FPITCH) + bv_col;
#pragma unroll
            for (int d = 0; d < 8; d++) {
                uint32_t bvh[4], bvl[4];
                ldsm_x4_t(bvh, vrow + VH_O + d * 32);
                ldsm_x4_t(bvl, vrow + VL_O + d * 32);
                mma_bf16(o[2*d],   aph, &bvh[0]);
                mma_bf16(o[2*d+1], aph, &bvh[2]);
                mma_bf16(o[2*d],   aph, &bvl[0]);
                mma_bf16(o[2*d+1], aph, &bvl[2]);
                mma_bf16(o[2*d],   apl, &bvh[0]);
                mma_bf16(o[2*d+1], apl, &bvh[2]);
            }
        }
        __syncthreads();
        if (kt + 2 < NT) load_kv(kt + 2, kt & 1);
    }

    // ---- epilogue: write bf16 split of normalized output ----
    float i0 = 1.f / l0, i1 = 1.f / l1;
    const int row0 = q0 + wid * 16 + g;
#pragma unroll
    for (int nt = 0; nt < 16; nt++) {
        int col = head * HD + nt * 8 + 2 * t4;
        uint32_t h0, lo0, h1, lo1;
        split2(o[nt][0] * i0, o[nt][1] * i0, h0, lo0);
        split2(o[nt][2] * i1, o[nt][3] * i1, h1, lo1);
        size_t i32a = ((size_t)row0 * DIM + col) >> 1;
        size_t i32b = ((size_t)(row0 + 8) * DIM + col) >> 1;
        AOh[i32a] = h0; AOl[i32a] = lo0;
        AOh[i32b] = h1; AOl[i32b] = lo1;
    }
}

// ---------------- launcher ---------------------------------------------------
extern "C" void kernel_launch(void* const* d_in, const int* in_sizes, int n_in,
                              void* d_out, int out_size)
{
    const float* x     = (const float*)d_in[0];
    const float* freqs = (const float*)d_in[1];
    const float* wq    = (const float*)d_in[2];
    const float* bq    = (const float*)d_in[3];
    const float* wk    = (const float*)d_in[4];
    const float* bk    = (const float*)d_in[5];
    const float* wv    = (const float*)d_in[6];
    const float* bv    = (const float*)d_in[7];
    const float* wo    = (const float*)d_in[8];
    const float* bo    = (const float*)d_in[9];
    const float* gq    = (const float*)d_in[10];
    const float* gk    = (const float*)d_in[11];
    const int*   seq_lens   = (const int*)d_in[12];
    const int*   grid_sizes = (const int*)d_in[13];
    float* out = (float*)d_out;

    float *q, *k;
    uint4 *xh, *xl, *wh, *wl, *oh, *ol, *qh, *ql, *kh, *kl, *vh, *vl, *aoh, *aol;
    cudaGetSymbolAddress((void**)&q,   g_q);
    cudaGetSymbolAddress((void**)&k,   g_k);
    cudaGetSymbolAddress((void**)&xh,  g_xh);
    cudaGetSymbolAddress((void**)&xl,  g_xl);
    cudaGetSymbolAddress((void**)&wh,  g_wh);
    cudaGetSymbolAddress((void**)&wl,  g_wl);
    cudaGetSymbolAddress((void**)&oh,  g_oh);
    cudaGetSymbolAddress((void**)&ol,  g_ol);
    cudaGetSymbolAddress((void**)&qh,  g_qh);
    cudaGetSymbolAddress((void**)&ql,  g_ql);
    cudaGetSymbolAddress((void**)&kh,  g_kh);
    cudaGetSymbolAddress((void**)&kl,  g_kl);
    cudaGetSymbolAddress((void**)&vh,  g_vh);
    cudaGetSymbolAddress((void**)&vl,  g_vl);
    cudaGetSymbolAddress((void**)&aoh, g_aoh);
    cudaGetSymbolAddress((void**)&aol, g_aol);

    const int n8x = S_LEN * DIM / 8;
    const int n8w = DIM * DIM / 8;
    const float qscale = 1.0f / sqrtf((float)HD);

    // launch 0: x split
    conv_split<<<(n8x + 255) / 256, 256>>>((const float4*)x, xh, xl, n8x);
    // launch 1: wq|wk|wv split (batched)
    conv_split_w3<<<dim3((n8w + 255) / 256, 3), 256>>>(
        (const float4*)wq, (const float4*)wk, (const float4*)wv, wh, wl, n8w);
    // launch 2: wo split
    conv_split<<<(n8w + 255) / 256, 256>>>((const float4*)wo, oh, ol, n8w);

    cudaFuncSetAttribute(gemm_mma, cudaFuncAttributeMaxDynamicSharedMemorySize, GEMM_SMEM);

    // launch 3: fused QKV gemm (V written as split directly)
    gemm_mma<<<dim3(S_LEN / 128, 36), 256, GEMM_SMEM>>>(
        xh, xl, wh, wl, bq, bk, bv, q, k,
        (uint32_t*)vh, (uint32_t*)vl, DIM / 128);

    // launch 4: norm+rope -> Q/K splits (Q pre-scaled)
    norm_rope_split<<<S_LEN, 256>>>(q, k, gq, gk, freqs, grid_sizes,
                                    (uint32_t*)qh, (uint32_t*)ql,
                                    (uint32_t*)kh, (uint32_t*)kl, qscale);

    // launch 5: flash attention (profiled by ncu -s 5)
    cudaFuncSetAttribute(flash_mma, cudaFuncAttributeMaxDynamicSharedMemorySize, FL_SMEM);
    flash_mma<<<dim3(S_LEN / FQT, NH), 256, FL_SMEM>>>(
        qh, ql, kh, kl, vh, vl, (uint32_t*)aoh, (uint32_t*)aol, seq_lens);

    // launch 6: output projection
    gemm_mma<<<dim3(S_LEN / 128, 12), 256, GEMM_SMEM>>>(
        aoh, aol, oh, ol, bo, bo, bo, out, out,
        (uint32_t*)vh, (uint32_t*)vl, DIM / 128);
}

// round 6
// speedup vs baseline: 1.0084x; 1.0084x over previous
#include <cuda_runtime.h>
#include <cuda_bf16.h>
#include <math.h>
#include <stdint.h>

// Problem constants
#define S_LEN 2048
#define DIM   1536
#define NH    12
#define HD    128
#define CHALF (HD/2)
#define SEG0  22
#define SEG1  21

// ---------------- scratch (device globals) ----------------------------------
__device__ float g_q[S_LEN * DIM];
__device__ float g_k[S_LEN * DIM];

__device__ uint4 g_qh[S_LEN * DIM / 8];
__device__ uint4 g_ql[S_LEN * DIM / 8];
__device__ uint4 g_wh[3 * DIM * DIM / 8];   // wq|wk|wv split
__device__ uint4 g_wl[3 * DIM * DIM / 8];
__device__ uint4 g_oh[DIM * DIM / 8];       // wo split
__device__ uint4 g_ol[DIM * DIM / 8];
__device__ uint4 g_kh[S_LEN * DIM / 8];
__device__ uint4 g_kl[S_LEN * DIM / 8];
__device__ uint4 g_vh[S_LEN * DIM / 8];
__device__ uint4 g_vl[S_LEN * DIM / 8];
__device__ uint4 g_aoh[S_LEN * DIM / 8];
__device__ uint4 g_aol[S_LEN * DIM / 8];
__device__ uint4 g_xh[S_LEN * DIM / 8];
__device__ uint4 g_xl[S_LEN * DIM / 8];

// ---------------- PTX helpers ------------------------------------------------
__device__ __forceinline__ uint32_t smem_u32(const void* p) {
    uint32_t a;
    asm("{ .reg .u64 t; cvta.to.shared.u64 t, %1; cvt.u32.u64 %0, t; }" : "=r"(a) : "l"(p));
    return a;
}
__device__ __forceinline__ void ldsm_x4(uint32_t* r, uint32_t addr) {
    asm volatile("ldmatrix.sync.aligned.m8n8.x4.shared.b16 {%0,%1,%2,%3}, [%4];"
        : "=r"(r[0]), "=r"(r[1]), "=r"(r[2]), "=r"(r[3]) : "r"(addr));
}
__device__ __forceinline__ void ldsm_x4_t(uint32_t* r, uint32_t addr) {
    asm volatile("ldmatrix.sync.aligned.m8n8.x4.trans.shared.b16 {%0,%1,%2,%3}, [%4];"
        : "=r"(r[0]), "=r"(r[1]), "=r"(r[2]), "=r"(r[3]) : "r"(addr));
}
__device__ __forceinline__ void mma_bf16(float* c, const uint32_t* a, const uint32_t* b) {
    asm volatile(
        "mma.sync.aligned.m16n8k16.row.col.f32.bf16.bf16.f32 "
        "{%0,%1,%2,%3}, {%4,%5,%6,%7}, {%8,%9}, {%0,%1,%2,%3};"
        : "+f"(c[0]), "+f"(c[1]), "+f"(c[2]), "+f"(c[3])
        : "r"(a[0]), "r"(a[1]), "r"(a[2]), "r"(a[3]), "r"(b[0]), "r"(b[1]));
}
__device__ __forceinline__ void cp16(uint32_t dst, const void* src) {
    asm volatile("cp.async.cg.shared.global [%0], [%1], 16;" :: "r"(dst), "l"(src));
}
#define CP_COMMIT()  asm volatile("cp.async.commit_group;" ::: "memory")
#define CP_WAIT(n)   asm volatile("cp.async.wait_group %0;" :: "n"(n) : "memory")

__device__ __forceinline__ void split2(float v0, float v1, uint32_t& h, uint32_t& l) {
    __nv_bfloat16 h0 = __float2bfloat16_rn(v0);
    __nv_bfloat16 h1 = __float2bfloat16_rn(v1);
    __nv_bfloat16 l0 = __float2bfloat16_rn(v0 - __bfloat162float(h0));
    __nv_bfloat16 l1 = __float2bfloat16_rn(v1 - __bfloat162float(h1));
    h = (uint32_t)__bfloat16_as_ushort(h0) | ((uint32_t)__bfloat16_as_ushort(h1) << 16);
    l = (uint32_t)__bfloat16_as_ushort(l0) | ((uint32_t)__bfloat16_as_ushort(l1) << 16);
}

// ---------------- fp32 -> bf16 hi/lo split ------------------------------------
__global__ __launch_bounds__(256)
void conv_split(const float4* __restrict__ src, uint4* __restrict__ hi,
                uint4* __restrict__ lo, int n8)
{
    int idx = blockIdx.x * blockDim.x + threadIdx.x;
    if (idx >= n8) return;
    float4 a = src[2 * idx], b = src[2 * idx + 1];
    float xs[8] = {a.x, a.y, a.z, a.w, b.x, b.y, b.z, b.w};
    uint32_t h[4], l[4];
#pragma unroll
    for (int i = 0; i < 4; i++) split2(xs[2 * i], xs[2 * i + 1], h[i], l[i]);
    hi[idx] = make_uint4(h[0], h[1], h[2], h[3]);
    lo[idx] = make_uint4(l[0], l[1], l[2], l[3]);
}

__global__ __launch_bounds__(256)
void conv_split_w3(const float4* __restrict__ w0, const float4* __restrict__ w1,
                   const float4* __restrict__ w2, uint4* __restrict__ hi,
                   uint4* __restrict__ lo, int n8)
{
    int idx = blockIdx.x * blockDim.x + threadIdx.x;
    if (idx >= n8) return;
    const float4* src = (blockIdx.y == 0) ? w0 : (blockIdx.y == 1) ? w1 : w2;
    size_t off = (size_t)blockIdx.y * n8;
    float4 a = src[2 * idx], b = src[2 * idx + 1];
    float xs[8] = {a.x, a.y, a.z, a.w, b.x, b.y, b.z, b.w};
    uint32_t h[4], l[4];
#pragma unroll
    for (int i = 0; i < 4; i++) split2(xs[2 * i], xs[2 * i + 1], h[i], l[i]);
    hi[off + idx] = make_uint4(h[0], h[1], h[2], h[3]);
    lo[off + idx] = make_uint4(l[0], l[1], l[2], l[3]);
}

// ---------------- bf16-split GEMM via mma.sync --------------------------------
#define PITCH  80
#define TILEB  (128 * PITCH)
#define STAGEB (4 * TILEB)
#define GEMM_SMEM (2 * STAGEB)
#define NSTAGE 48

__global__ __launch_bounds__(256, 2)       // force 2 CTAs/SM
void gemm_mma(const uint4* __restrict__ Ah, const uint4* __restrict__ Al,
              const uint4* __restrict__ Wh, const uint4* __restrict__ Wl,
              const float* __restrict__ b0, const float* __restrict__ b1,
              const float* __restrict__ b2,
              float* __restrict__ C0, float* __restrict__ C1,
              uint32_t* __restrict__ Vh, uint32_t* __restrict__ Vl,
              int ntw)
{
    extern __shared__ char smc[];
    const uint32_t sb = smem_u32(smc);
    const int tid  = threadIdx.x;
    const int wid  = tid >> 5;
    const int lane = tid & 31;
    const int warp_m = wid & 1;
    const int warp_n = wid >> 1;

    const int m0     = blockIdx.x * 128;
    const int ntile  = blockIdx.y;
    const int w      = ntile / ntw;
    const int ncol0  = (ntile % ntw) * 128;
    const size_t wrow0 = (size_t)ntile * 128;

    const int lr = tid >> 2;
    const int lj = tid & 3;

    float acc[4][4][4];
#pragma unroll
    for (int i = 0; i < 4; i++)
#pragma unroll
        for (int j = 0; j < 4; j++)
#pragma unroll
            for (int k = 0; k < 4; k++) acc[i][j][k] = 0.f;

    auto prefetch = [&](int c, int buf) {
        const uint32_t st = sb + buf * STAGEB;
        const int kc4 = c * 4;
#pragma unroll
        for (int i = 0; i < 2; i++) {
            int r = lr + i * 64;
            uint32_t so = (uint32_t)(r * PITCH + lj * 16);
            size_t ga = (size_t)(m0 + r) * (DIM / 8) + kc4 + lj;
            cp16(st + 0 * TILEB + so, Ah + ga);
            cp16(st + 1 * TILEB + so, Al + ga);
            size_t gb = (wrow0 + r) * (DIM / 8) + kc4 + lj;
            cp16(st + 2 * TILEB + so, Wh + gb);
            cp16(st + 3 * TILEB + so, Wl + gb);
        }
        CP_COMMIT();
    };

    prefetch(0, 0);
    prefetch(1, 1);

    const uint32_t a_lo = (uint32_t)((warp_m * 64 + (lane & 15)) * PITCH + (lane >> 4) * 16);
    const uint32_t b_lo = (uint32_t)((warp_n * 32 + (lane & 7) + ((lane >> 4) << 3)) * PITCH
                                     + ((lane >> 3) & 1) * 16);

    for (int c = 0; c < NSTAGE; c++) {
        if (c < NSTAGE - 1) { CP_WAIT(1); } else { CP_WAIT(0); }
        __syncthreads();

        const uint32_t st = sb + (c & 1) * STAGEB;
#pragma unroll
        for (int ks = 0; ks < 2; ks++) {
            uint32_t ah[4][4], al[4][4], bh[2][4], bl[2][4];
#pragma unroll
            for (int mt = 0; mt < 4; mt++) {
                uint32_t base = st + mt * (16 * PITCH) + ks * 32 + a_lo;
                ldsm_x4(ah[mt], base);
                ldsm_x4(al[mt], base + TILEB);
            }
#pragma unroll
            for (int np = 0; np < 2; np++) {
                uint32_t base = st + 2 * TILEB + np * (16 * PITCH) + ks * 32 + b_lo;
                ldsm_x4(bh[np], base);
                ldsm_x4(bl[np], base + TILEB);
            }
#pragma unroll
            for (int mt = 0; mt < 4; mt++) {
#pragma unroll
                for (int nt = 0; nt < 4; nt++) {
                    const uint32_t* bhp = &bh[nt >> 1][(nt & 1) * 2];
                    const uint32_t* blp = &bl[nt >> 1][(nt & 1) * 2];
                    mma_bf16(acc[mt][nt], ah[mt], bhp);
                    mma_bf16(acc[mt][nt], ah[mt], blp);
                    mma_bf16(acc[mt][nt], al[mt], bhp);
                }
            }
        }
        __syncthreads();
        if (c + 2 < NSTAGE) prefetch(c + 2, c & 1);
    }

    const float* bias = (w == 0) ? b0 : (w == 1) ? b1 : b2;
    const int g = lane >> 2, t4 = lane & 3;

    if (w < 2) {
        float* C = (w == 0) ? C0 : C1;
#pragma unroll
        for (int mt = 0; mt < 4; mt++) {
            int row = m0 + warp_m * 64 + mt * 16 + g;
#pragma unroll
            for (int nt = 0; nt < 4; nt++) {
                int col = ncol0 + warp_n * 32 + nt * 8 + t4 * 2;
                float2 bv = *(const float2*)(bias + col);
                float2 o0, o1;
                o0.x = acc[mt][nt][0] + bv.x;  o0.y = acc[mt][nt][1] + bv.y;
                o1.x = acc[mt][nt][2] + bv.x;  o1.y = acc[mt][nt][3] + bv.y;
                *(float2*)(C + (size_t)row * DIM + col)       = o0;
                *(float2*)(C + (size_t)(row + 8) * DIM + col) = o1;
            }
        }
    } else {
#pragma unroll
        for (int mt = 0; mt < 4; mt++) {
            int row = m0 + warp_m * 64 + mt * 16 + g;
#pragma unroll
            for (int nt = 0; nt < 4; nt++) {
                int col = ncol0 + warp_n * 32 + nt * 8 + t4 * 2;
                float2 bv = *(const float2*)(bias + col);
                uint32_t h0, l0, h1, l1;
                split2(acc[mt][nt][0] + bv.x, acc[mt][nt][1] + bv.y, h0, l0);
                split2(acc[mt][nt][2] + bv.x, acc[mt][nt][3] + bv.y, h1, l1);
                size_t i0 = ((size_t)row * DIM + col) >> 1;
                size_t i1 = ((size_t)(row + 8) * DIM + col) >> 1;
                Vh[i0] = h0; Vl[i0] = l0;
                Vh[i1] = h1; Vl[i1] = l1;
            }
        }
    }
}

// ---------------- fused RMSNorm + RoPE -> bf16 splits -------------------------
__global__ __launch_bounds__(256)
void norm_rope_split(const float* __restrict__ Q, const float* __restrict__ K,
                     const float* __restrict__ gq, const float* __restrict__ gk,
                     const float* __restrict__ freqs, const int* __restrict__ grid_sizes,
                     uint32_t* __restrict__ Qh, uint32_t* __restrict__ Ql,
                     uint32_t* __restrict__ Kh, uint32_t* __restrict__ Kl,
                     float qscale)
{
    const int s   = blockIdx.x;
    const int tid = threadIdx.x;
    __shared__ float red[256];
    __shared__ float s_rq, s_rk;

    const float* qrow = Q + (size_t)s * DIM;
    const float* krow = K + (size_t)s * DIM;

    float sq = 0.f, sk = 0.f;
    for (int i = tid; i < DIM; i += 256) {
        float a = qrow[i]; sq += a * a;
        float b = krow[i]; sk += b * b;
    }
    red[tid] = sq; __syncthreads();
    for (int off = 128; off > 0; off >>= 1) {
        if (tid < off) red[tid] += red[tid + off];
        __syncthreads();
    }
    if (tid == 0) s_rq = rsqrtf(red[0] * (1.f / DIM) + 1e-6f);
    __syncthreads();
    red[tid] = sk; __syncthreads();
    for (int off = 128; off > 0; off >>= 1) {
        if (tid < off) red[tid] += red[tid + off];
        __syncthreads();
    }
    if (tid == 0) s_rk = rsqrtf(red[0] * (1.f / DIM) + 1e-6f);
    __syncthreads();

    const float rq = s_rq, rk = s_rk;

    const int hdim = grid_sizes[1];
    const int wdim = grid_sizes[2];
    const int wi = s % wdim;
    const int hi = (s / wdim) % hdim;
    const int fi = s / (wdim * hdim);

    for (int p = tid; p < NH * CHALF; p += 256) {
        const int head = p >> 6;
        const int c    = p & 63;
        int pos = (c < SEG0) ? fi : ((c < SEG0 + SEG1) ? hi : wi);
        float ang = freqs[(size_t)pos * CHALF + c];
        float sn, cs;
        sincosf(ang, &sn, &cs);

        const int d0 = head * HD + 2 * c;
        float q0 = qrow[d0]     * rq * gq[d0];
        float q1 = qrow[d0 + 1] * rq * gq[d0 + 1];
        float qv0 = (q0 * cs - q1 * sn) * qscale;
        float qv1 = (q0 * sn + q1 * cs) * qscale;

        float k0 = krow[d0]     * rk * gk[d0];
        float k1 = krow[d0 + 1] * rk * gk[d0 + 1];
        float kv0 = k0 * cs - k1 * sn;
        float kv1 = k0 * sn + k1 * cs;

        size_t i32 = ((size_t)s * DIM + d0) >> 1;
        uint32_t h, l;
        split2(qv0, qv1, h, l); Qh[i32] = h; Ql[i32] = l;
        split2(kv0, kv1, h, l); Kh[i32] = h; Kl[i32] = l;
    }
}

// ---------------- flash attention: 3-stage KV ring ----------------------------
#define FQT    128
#define FKT    64
#define FPITCH 272
#define QH_OFF 0
#define QL_OFF (128 * FPITCH)           // 34816
#define KH_O   0
#define KL_O   (64 * FPITCH)
#define VH_O   (2 * 64 * FPITCH)
#define VL_O   (3 * 64 * FPITCH)
#define STG_SZ (4 * 64 * FPITCH)        // 69632 (== Q staging size)
#define FL_SMEM (3 * STG_SZ)            // 208896

__global__ __launch_bounds__(256, 1)
void flash_mma(const uint4* __restrict__ Qh, const uint4* __restrict__ Ql,
               const uint4* __restrict__ Kh, const uint4* __restrict__ Kl,
               const uint4* __restrict__ Vh, const uint4* __restrict__ Vl,
               uint32_t* __restrict__ AOh, uint32_t* __restrict__ AOl,
               const int* __restrict__ seq_lens)
{
    extern __shared__ char smc[];
    const uint32_t sb = smem_u32(smc);
    const int tid  = threadIdx.x;
    const int wid  = tid >> 5;
    const int lane = tid & 31;
    const int g    = lane >> 2;
    const int t4   = lane & 3;
    const int head = blockIdx.y;
    const int q0   = blockIdx.x * FQT;
    const int seqlen = seq_lens[0];

    const int DIM8 = DIM / 8;
    const int h8   = head * (HD / 8);

    // stage Q (hi/lo) into slot 0 region, consumed into registers below
#pragma unroll
    for (int i = 0; i < 8; i++) {
        int t = tid + 256 * i;
        int r = t >> 4, j = t & 15;
        uint32_t so = (uint32_t)(r * FPITCH + j * 16);
        size_t gi = (size_t)(q0 + r) * DIM8 + h8 + j;
        cp16(sb + QH_OFF + so, Qh + gi);
        cp16(sb + QL_OFF + so, Ql + gi);
    }
    CP_COMMIT();

    const uint32_t a_off  = (uint32_t)((wid * 16 + (lane & 15)) * FPITCH + (lane >> 4) * 16);
    const uint32_t bk_off = (uint32_t)(((lane & 7) + ((lane >> 4) << 3)) * FPITCH
                                       + ((lane >> 3) & 1) * 16);
    const uint32_t bv_row = (uint32_t)((lane & 7) + (((lane >> 3) & 1) << 3));
    const uint32_t bv_col = (uint32_t)((lane >> 4) * 16);

    // extract Q fragments to registers
    CP_WAIT(0);
    __syncthreads();
    uint32_t qhf[8][4], qlf[8][4];
#pragma unroll
    for (int kk = 0; kk < 8; kk++) {
        ldsm_x4(qhf[kk], sb + QH_OFF + a_off + kk * 32);
        ldsm_x4(qlf[kk], sb + QL_OFF + a_off + kk * 32);
    }
    __syncthreads();    // slot 0 free for KV ring

    auto load_kv = [&](int kt, int slot) {
        uint32_t st = sb + slot * STG_SZ;
        int kr0 = kt * FKT;
#pragma unroll
        for (int i = 0; i < 4; i++) {
            int t = tid + 256 * i;
            int r = t >> 4, j = t & 15;
            uint32_t so = (uint32_t)(r * FPITCH + j * 16);
            size_t gi = (size_t)(kr0 + r) * DIM8 + h8 + j;
            cp16(st + KH_O + so, Kh + gi);
            cp16(st + KL_O + so, Kl + gi);
            cp16(st + VH_O + so, Vh + gi);
            cp16(st + VL_O + so, Vl + gi);
        }
        CP_COMMIT();
    };

    load_kv(0, 0);
    load_kv(1, 1);
    load_kv(2, 2);

    float o[16][4];
#pragma unroll
    for (int i = 0; i < 16; i++)
#pragma unroll
        for (int j = 0; j < 4; j++) o[i][j] = 0.f;
    float m0 = -1e30f, m1 = -1e30f, l0 = 0.f, l1 = 0.f;

    const int NT = S_LEN / FKT;     // 32
    int slot = 0;
    for (int kt = 0; kt < NT; kt++) {
        if (kt < NT - 2)      { CP_WAIT(2); }
        else if (kt == NT - 2){ CP_WAIT(1); }
        else                  { CP_WAIT(0); }
        __syncthreads();
        const uint32_t st = sb + slot * STG_SZ;

        // ---- scores ----
        float acc[8][4];
#pragma unroll
        for (int i = 0; i < 8; i++)
#pragma unroll
            for (int j = 0; j < 4; j++) acc[i][j] = 0.f;

#pragma unroll
        for (int kk = 0; kk < 8; kk++) {
#pragma unroll
            for (int np = 0; np < 4; np++) {
                uint32_t bh[4], bl[4];
                uint32_t kb = st + np * (16 * FPITCH) + bk_off + kk * 32;
                ldsm_x4(bh, kb + KH_O);
                ldsm_x4(bl, kb + KL_O);
                mma_bf16(acc[2*np],   qhf[kk], &bh[0]);
                mma_bf16(acc[2*np+1], qhf[kk], &bh[2]);
                mma_bf16(acc[2*np],   qhf[kk], &bl[0]);
                mma_bf16(acc[2*np+1], qhf[kk], &bl[2]);
                mma_bf16(acc[2*np],   qlf[kk], &bh[0]);
                mma_bf16(acc[2*np+1], qlf[kk], &bh[2]);
            }
        }

        // ---- mask + online softmax ----
        const int kr0 = kt * FKT;
        float mx0 = -1e30f, mx1 = -1e30f;
#pragma unroll
        for (int j = 0; j < 8; j++) {
            int c0 = kr0 + 8 * j + 2 * t4;
            if (c0 >= seqlen)     { acc[j][0] = -1e30f; acc[j][2] = -1e30f; }
            if (c0 + 1 >= seqlen) { acc[j][1] = -1e30f; acc[j][3] = -1e30f; }
            mx0 = fmaxf(mx0, fmaxf(acc[j][0], acc[j][1]));
            mx1 = fmaxf(mx1, fmaxf(acc[j][2], acc[j][3]));
        }
        mx0 = fmaxf(mx0, __shfl_xor_sync(0xffffffffu, mx0, 1));
        mx0 = fmaxf(mx0, __shfl_xor_sync(0xffffffffu, mx0, 2));
        mx1 = fmaxf(mx1, __shfl_xor_sync(0xffffffffu, mx1, 1));
        mx1 = fmaxf(mx1, __shfl_xor_sync(0xffffffffu, mx1, 2));

        float mn0 = fmaxf(m0, mx0), mn1 = fmaxf(m1, mx1);
        float al0 = __expf(m0 - mn0), al1 = __expf(m1 - mn1);
        m0 = mn0; m1 = mn1;

        float s0 = 0.f, s1 = 0.f;
        uint32_t ph0[8], ph1[8], pl0[8], pl1[8];
#pragma unroll
        for (int j = 0; j < 8; j++) {
            float p00 = __expf(acc[j][0] - mn0);
            float p01 = __expf(acc[j][1] - mn0);
            float p10 = __expf(acc[j][2] - mn1);
            float p11 = __expf(acc[j][3] - mn1);
            s0 += p00 + p01;
            s1 += p10 + p11;
            split2(p00, p01, ph0[j], pl0[j]);
            split2(p10, p11, ph1[j], pl1[j]);
        }
        s0 += __shfl_xor_sync(0xffffffffu, s0, 1);
        s0 += __shfl_xor_sync(0xffffffffu, s0, 2);
        s1 += __shfl_xor_sync(0xffffffffu, s1, 1);
        s1 += __shfl_xor_sync(0xffffffffu, s1, 2);
        l0 = l0 * al0 + s0;
        l1 = l1 * al1 + s1;

#pragma unroll
        for (int nt = 0; nt < 16; nt++) {
            o[nt][0] *= al0; o[nt][1] *= al0;
            o[nt][2] *= al1; o[nt][3] *= al1;
        }

        // ---- PV ----
#pragma unroll
        for (int k2 = 0; k2 < 4; k2++) {
            uint32_t aph[4] = { ph0[2*k2], ph1[2*k2], ph0[2*k2+1], ph1[2*k2+1] };
            uint32_t apl[4] = { pl0[2*k2], pl1[2*k2], pl0[2*k2+1], pl1[2*k2+1] };
            uint32_t vrow = st + (uint32_t)((k2 * 16 + bv_row) * FPITCH) + bv_col;
#pragma unroll
            for (int d = 0; d < 8; d++) {
                uint32_t bvh[4], bvl[4];
                ldsm_x4_t(bvh, vrow + VH_O + d * 32);
                ldsm_x4_t(bvl, vrow + VL_O + d * 32);
                mma_bf16(o[2*d],   aph, &bvh[0]);
                mma_bf16(o[2*d+1], aph, &bvh[2]);
                mma_bf16(o[2*d],   aph, &bvl[0]);
                mma_bf16(o[2*d+1], aph, &bvl[2]);
                mma_bf16(o[2*d],   apl, &bvh[0]);
                mma_bf16(o[2*d+1], apl, &bvh[2]);
            }
        }
        __syncthreads();
        if (kt + 3 < NT) load_kv(kt + 3, slot);
        slot = (slot == 2) ? 0 : slot + 1;
    }

    // ---- epilogue: write bf16 split of normalized output ----
    float i0 = 1.f / l0, i1 = 1.f / l1;
    const int row0 = q0 + wid * 16 + g;
#pragma unroll
    for (int nt = 0; nt < 16; nt++) {
        int col = head * HD + nt * 8 + 2 * t4;
        uint32_t h0, lo0, h1, lo1;
        split2(o[nt][0] * i0, o[nt][1] * i0, h0, lo0);
        split2(o[nt][2] * i1, o[nt][3] * i1, h1, lo1);
        size_t i32a = ((size_t)row0 * DIM + col) >> 1;
        size_t i32b = ((size_t)(row0 + 8) * DIM + col) >> 1;
        AOh[i32a] = h0; AOl[i32a] = lo0;
        AOh[i32b] = h1; AOl[i32b] = lo1;
    }
}

// ---------------- launcher ---------------------------------------------------
extern "C" void kernel_launch(void* const* d_in, const int* in_sizes, int n_in,
                              void* d_out, int out_size)
{
    const float* x     = (const float*)d_in[0];
    const float* freqs = (const float*)d_in[1];
    const float* wq    = (const float*)d_in[2];
    const float* bq    = (const float*)d_in[3];
    const float* wk    = (const float*)d_in[4];
    const float* bk    = (const float*)d_in[5];
    const float* wv    = (const float*)d_in[6];
    const float* bv    = (const float*)d_in[7];
    const float* wo    = (const float*)d_in[8];
    const float* bo    = (const float*)d_in[9];
    const float* gq    = (const float*)d_in[10];
    const float* gk    = (const float*)d_in[11];
    const int*   seq_lens   = (const int*)d_in[12];
    const int*   grid_sizes = (const int*)d_in[13];
    float* out = (float*)d_out;

    float *q, *k;
    uint4 *xh, *xl, *wh, *wl, *oh, *ol, *qh, *ql, *kh, *kl, *vh, *vl, *aoh, *aol;
    cudaGetSymbolAddress((void**)&q,   g_q);
    cudaGetSymbolAddress((void**)&k,   g_k);
    cudaGetSymbolAddress((void**)&xh,  g_xh);
    cudaGetSymbolAddress((void**)&xl,  g_xl);
    cudaGetSymbolAddress((void**)&wh,  g_wh);
    cudaGetSymbolAddress((void**)&wl,  g_wl);
    cudaGetSymbolAddress((void**)&oh,  g_oh);
    cudaGetSymbolAddress((void**)&ol,  g_ol);
    cudaGetSymbolAddress((void**)&qh,  g_qh);
    cudaGetSymbolAddress((void**)&ql,  g_ql);
    cudaGetSymbolAddress((void**)&kh,  g_kh);
    cudaGetSymbolAddress((void**)&kl,  g_kl);
    cudaGetSymbolAddress((void**)&vh,  g_vh);
    cudaGetSymbolAddress((void**)&vl,  g_vl);
    cudaGetSymbolAddress((void**)&aoh, g_aoh);
    cudaGetSymbolAddress((void**)&aol, g_aol);

    const int n8x = S_LEN * DIM / 8;
    const int n8w = DIM * DIM / 8;
    const float qscale = 1.0f / sqrtf((float)HD);

    conv_split<<<(n8x + 255) / 256, 256>>>((const float4*)x, xh, xl, n8x);
    conv_split_w3<<<dim3((n8w + 255) / 256, 3), 256>>>(
        (const float4*)wq, (const float4*)wk, (const float4*)wv, wh, wl, n8w);
    conv_split<<<(n8w + 255) / 256, 256>>>((const float4*)wo, oh, ol, n8w);

    cudaFuncSetAttribute(gemm_mma, cudaFuncAttributeMaxDynamicSharedMemorySize, GEMM_SMEM);

    gemm_mma<<<dim3(S_LEN / 128, 36), 256, GEMM_SMEM>>>(
        xh, xl, wh, wl, bq, bk, bv, q, k,
        (uint32_t*)vh, (uint32_t*)vl, DIM / 128);

    norm_rope_split<<<S_LEN, 256>>>(q, k, gq, gk, freqs, grid_sizes,
                                    (uint32_t*)qh, (uint32_t*)ql,
                                    (uint32_t*)kh, (uint32_t*)kl, qscale);

    cudaFuncSetAttribute(flash_mma, cudaFuncAttributeMaxDynamicSharedMemorySize, FL_SMEM);
    flash_mma<<<dim3(S_LEN / FQT, NH), 256, FL_SMEM>>>(
        qh, ql, kh, kl, vh, vl, (uint32_t*)aoh, (uint32_t*)aol, seq_lens);

    gemm_mma<<<dim3(S_LEN / 128, 12), 256, GEMM_SMEM>>>(
        aoh, aol, oh, ol, bo, bo, bo, out, out,
        (uint32_t*)vh, (uint32_t*)vl, DIM / 128);
}

// round 7
// speedup vs baseline: 1.4543x; 1.4422x over previous
#include <cuda_runtime.h>
#include <cuda_fp16.h>
#include <math.h>
#include <stdint.h>

// Problem constants
#define S_LEN 2048
#define DIM   1536
#define NH    12
#define HD    128
#define CHALF (HD/2)
#define SEG0  22
#define SEG1  21

// ---------------- scratch (device globals) ----------------------------------
__device__ float g_q[S_LEN * DIM];
__device__ float g_k[S_LEN * DIM];

__device__ uint4 g_xh[S_LEN * DIM / 8];     // x fp16 split
__device__ uint4 g_xl[S_LEN * DIM / 8];
__device__ uint4 g_w16[3 * DIM * DIM / 8];  // wq|wk|wv single fp16
__device__ uint4 g_wo16[DIM * DIM / 8];     // wo single fp16
__device__ uint4 g_qh[S_LEN * DIM / 8];     // Q fp16 split (post norm/rope)
__device__ uint4 g_ql[S_LEN * DIM / 8];
__device__ uint4 g_k16[S_LEN * DIM / 8];    // K single fp16
__device__ uint4 g_v16[S_LEN * DIM / 8];    // V single fp16
__device__ uint4 g_aoh[S_LEN * DIM / 8];    // attn out fp16 split
__device__ uint4 g_aol[S_LEN * DIM / 8];

// ---------------- PTX helpers ------------------------------------------------
__device__ __forceinline__ uint32_t smem_u32(const void* p) {
    uint32_t a;
    asm("{ .reg .u64 t; cvta.to.shared.u64 t, %1; cvt.u32.u64 %0, t; }" : "=r"(a) : "l"(p));
    return a;
}
__device__ __forceinline__ void ldsm_x4(uint32_t* r, uint32_t addr) {
    asm volatile("ldmatrix.sync.aligned.m8n8.x4.shared.b16 {%0,%1,%2,%3}, [%4];"
        : "=r"(r[0]), "=r"(r[1]), "=r"(r[2]), "=r"(r[3]) : "r"(addr));
}
__device__ __forceinline__ void ldsm_x4_t(uint32_t* r, uint32_t addr) {
    asm volatile("ldmatrix.sync.aligned.m8n8.x4.trans.shared.b16 {%0,%1,%2,%3}, [%4];"
        : "=r"(r[0]), "=r"(r[1]), "=r"(r[2]), "=r"(r[3]) : "r"(addr));
}
__device__ __forceinline__ void mma_f16(float* c, const uint32_t* a, const uint32_t* b) {
    asm volatile(
        "mma.sync.aligned.m16n8k16.row.col.f32.f16.f16.f32 "
        "{%0,%1,%2,%3}, {%4,%5,%6,%7}, {%8,%9}, {%0,%1,%2,%3};"
        : "+f"(c[0]), "+f"(c[1]), "+f"(c[2]), "+f"(c[3])
        : "r"(a[0]), "r"(a[1]), "r"(a[2]), "r"(a[3]), "r"(b[0]), "r"(b[1]));
}
__device__ __forceinline__ void cp16(uint32_t dst, const void* src) {
    asm volatile("cp.async.cg.shared.global [%0], [%1], 16;" :: "r"(dst), "l"(src));
}
#define CP_COMMIT()  asm volatile("cp.async.commit_group;" ::: "memory")
#define CP_WAIT(n)   asm volatile("cp.async.wait_group %0;" :: "n"(n) : "memory")

__device__ __forceinline__ uint32_t pack2h(float v0, float v1) {
    __half h0 = __float2half_rn(v0);
    __half h1 = __float2half_rn(v1);
    return (uint32_t)__half_as_ushort(h0) | ((uint32_t)__half_as_ushort(h1) << 16);
}
__device__ __forceinline__ void split2h(float v0, float v1, uint32_t& h, uint32_t& l) {
    __half h0 = __float2half_rn(v0);
    __half h1 = __float2half_rn(v1);
    __half l0 = __float2half_rn(v0 - __half2float(h0));
    __half l1 = __float2half_rn(v1 - __half2float(h1));
    h = (uint32_t)__half_as_ushort(h0) | ((uint32_t)__half_as_ushort(h1) << 16);
    l = (uint32_t)__half_as_ushort(l0) | ((uint32_t)__half_as_ushort(l1) << 16);
}

// ---------------- conversions --------------------------------------------------
__global__ __launch_bounds__(256)
void conv_split_h2(const float4* __restrict__ src, uint4* __restrict__ hi,
                   uint4* __restrict__ lo, int n8)
{
    int idx = blockIdx.x * blockDim.x + threadIdx.x;
    if (idx >= n8) return;
    float4 a = src[2 * idx], b = src[2 * idx + 1];
    float xs[8] = {a.x, a.y, a.z, a.w, b.x, b.y, b.z, b.w};
    uint32_t h[4], l[4];
#pragma unroll
    for (int i = 0; i < 4; i++) split2h(xs[2 * i], xs[2 * i + 1], h[i], l[i]);
    hi[idx] = make_uint4(h[0], h[1], h[2], h[3]);
    lo[idx] = make_uint4(l[0], l[1], l[2], l[3]);
}

// batched single-fp16 conversion of up to 3 weights via blockIdx.y
__global__ __launch_bounds__(256)
void conv_h1_w3(const float4* __restrict__ w0, const float4* __restrict__ w1,
                const float4* __restrict__ w2, uint4* __restrict__ dst, int n8)
{
    int idx = blockIdx.x * blockDim.x + threadIdx.x;
    if (idx >= n8) return;
    const float4* src = (blockIdx.y == 0) ? w0 : (blockIdx.y == 1) ? w1 : w2;
    size_t off = (size_t)blockIdx.y * n8;
    float4 a = src[2 * idx], b = src[2 * idx + 1];
    dst[off + idx] = make_uint4(pack2h(a.x, a.y), pack2h(a.z, a.w),
                                pack2h(b.x, b.y), pack2h(b.z, b.w));
}

__global__ __launch_bounds__(256)
void conv_h1(const float4* __restrict__ src, uint4* __restrict__ dst, int n8)
{
    int idx = blockIdx.x * blockDim.x + threadIdx.x;
    if (idx >= n8) return;
    float4 a = src[2 * idx], b = src[2 * idx + 1];
    dst[idx] = make_uint4(pack2h(a.x, a.y), pack2h(a.z, a.w),
                          pack2h(b.x, b.y), pack2h(b.z, b.w));
}

// ---------------- fp16 2-term GEMM via mma.sync --------------------------------
// C = A @ W^T + bias;  A = Ah+Al (fp16 split), W single fp16.
// 3-stage ring, one barrier per stage. Stage tiles: Ah, Al, W.
#define PITCH  80
#define TILEB  (128 * PITCH)          // 10240
#define STAGEB (3 * TILEB)            // 30720
#define GEMM_SMEM (3 * STAGEB)        // 92160
#define NSTAGE 48

__global__ __launch_bounds__(256, 2)
void gemm_mma(const uint4* __restrict__ Ah, const uint4* __restrict__ Al,
              const uint4* __restrict__ W16,
              const float* __restrict__ b0, const float* __restrict__ b1,
              const float* __restrict__ b2,
              float* __restrict__ C0, float* __restrict__ C1,
              uint32_t* __restrict__ V16,
              int ntw)
{
    extern __shared__ char smc[];
    const uint32_t sb = smem_u32(smc);
    const int tid  = threadIdx.x;
    const int wid  = tid >> 5;
    const int lane = tid & 31;
    const int warp_m = wid & 1;
    const int warp_n = wid >> 1;

    const int m0     = blockIdx.x * 128;
    const int ntile  = blockIdx.y;
    const int w      = ntile / ntw;
    const int ncol0  = (ntile % ntw) * 128;
    const size_t wrow0 = (size_t)ntile * 128;

    const int lr = tid >> 2;
    const int lj = tid & 3;

    float acc[4][4][4];
#pragma unroll
    for (int i = 0; i < 4; i++)
#pragma unroll
        for (int j = 0; j < 4; j++)
#pragma unroll
            for (int k = 0; k < 4; k++) acc[i][j][k] = 0.f;

    auto prefetch = [&](int c, int buf) {
        const uint32_t st = sb + buf * STAGEB;
        const int kc4 = c * 4;
#pragma unroll
        for (int i = 0; i < 2; i++) {
            int r = lr + i * 64;
            uint32_t so = (uint32_t)(r * PITCH + lj * 16);
            size_t ga = (size_t)(m0 + r) * (DIM / 8) + kc4 + lj;
            cp16(st + 0 * TILEB + so, Ah + ga);
            cp16(st + 1 * TILEB + so, Al + ga);
            size_t gb = (wrow0 + r) * (DIM / 8) + kc4 + lj;
            cp16(st + 2 * TILEB + so, W16 + gb);
        }
        CP_COMMIT();
    };

    prefetch(0, 0);
    prefetch(1, 1);

    const uint32_t a_lo = (uint32_t)((warp_m * 64 + (lane & 15)) * PITCH + (lane >> 4) * 16);
    const uint32_t b_lo = (uint32_t)((warp_n * 32 + (lane & 7) + ((lane >> 4) << 3)) * PITCH
                                     + ((lane >> 3) & 1) * 16);

    int buf = 0;
    for (int c = 0; c < NSTAGE; c++) {
        if (c < NSTAGE - 1) { CP_WAIT(1); } else { CP_WAIT(0); }
        __syncthreads();
        // prefetch into the slot freed at the last barrier (c-1's slot == (c+2)%3)
        if (c + 2 < NSTAGE) prefetch(c + 2, (c + 2) % 3);

        const uint32_t st = sb + buf * STAGEB;
#pragma unroll
        for (int ks = 0; ks < 2; ks++) {
            uint32_t ah[4][4], al[4][4], bh[2][4];
#pragma unroll
            for (int mt = 0; mt < 4; mt++) {
                uint32_t base = st + mt * (16 * PITCH) + ks * 32 + a_lo;
                ldsm_x4(ah[mt], base);
                ldsm_x4(al[mt], base + TILEB);
            }
#pragma unroll
            for (int np = 0; np < 2; np++) {
                uint32_t base = st + 2 * TILEB + np * (16 * PITCH) + ks * 32 + b_lo;
                ldsm_x4(bh[np], base);
            }
#pragma unroll
            for (int mt = 0; mt < 4; mt++) {
#pragma unroll
                for (int nt = 0; nt < 4; nt++) {
                    const uint32_t* bhp = &bh[nt >> 1][(nt & 1) * 2];
                    mma_f16(acc[mt][nt], ah[mt], bhp);
                    mma_f16(acc[mt][nt], al[mt], bhp);
                }
            }
        }
        buf = (buf == 2) ? 0 : buf + 1;
    }

    const float* bias = (w == 0) ? b0 : (w == 1) ? b1 : b2;
    const int g = lane >> 2, t4 = lane & 3;

    if (w < 2) {
        float* C = (w == 0) ? C0 : C1;
#pragma unroll
        for (int mt = 0; mt < 4; mt++) {
            int row = m0 + warp_m * 64 + mt * 16 + g;
#pragma unroll
            for (int nt = 0; nt < 4; nt++) {
                int col = ncol0 + warp_n * 32 + nt * 8 + t4 * 2;
                float2 bv = *(const float2*)(bias + col);
                float2 o0, o1;
                o0.x = acc[mt][nt][0] + bv.x;  o0.y = acc[mt][nt][1] + bv.y;
                o1.x = acc[mt][nt][2] + bv.x;  o1.y = acc[mt][nt][3] + bv.y;
                *(float2*)(C + (size_t)row * DIM + col)       = o0;
                *(float2*)(C + (size_t)(row + 8) * DIM + col) = o1;
            }
        }
    } else {
        // V: write single fp16 directly
#pragma unroll
        for (int mt = 0; mt < 4; mt++) {
            int row = m0 + warp_m * 64 + mt * 16 + g;
#pragma unroll
            for (int nt = 0; nt < 4; nt++) {
                int col = ncol0 + warp_n * 32 + nt * 8 + t4 * 2;
                float2 bv = *(const float2*)(bias + col);
                size_t i0 = ((size_t)row * DIM + col) >> 1;
                size_t i1 = ((size_t)(row + 8) * DIM + col) >> 1;
                V16[i0] = pack2h(acc[mt][nt][0] + bv.x, acc[mt][nt][1] + bv.y);
                V16[i1] = pack2h(acc[mt][nt][2] + bv.x, acc[mt][nt][3] + bv.y);
            }
        }
    }
}

// ---------------- fused RMSNorm + RoPE -> fp16 outputs ------------------------
__global__ __launch_bounds__(256)
void norm_rope_split(const float* __restrict__ Q, const float* __restrict__ K,
                     const float* __restrict__ gq, const float* __restrict__ gk,
                     const float* __restrict__ freqs, const int* __restrict__ grid_sizes,
                     uint32_t* __restrict__ Qh, uint32_t* __restrict__ Ql,
                     uint32_t* __restrict__ K16)
{
    const int s   = blockIdx.x;
    const int tid = threadIdx.x;
    __shared__ float red[256];
    __shared__ float s_rq, s_rk;

    const float* qrow = Q + (size_t)s * DIM;
    const float* krow = K + (size_t)s * DIM;

    float sq = 0.f, sk = 0.f;
    for (int i = tid; i < DIM; i += 256) {
        float a = qrow[i]; sq += a * a;
        float b = krow[i]; sk += b * b;
    }
    red[tid] = sq; __syncthreads();
    for (int off = 128; off > 0; off >>= 1) {
        if (tid < off) red[tid] += red[tid + off];
        __syncthreads();
    }
    if (tid == 0) s_rq = rsqrtf(red[0] * (1.f / DIM) + 1e-6f);
    __syncthreads();
    red[tid] = sk; __syncthreads();
    for (int off = 128; off > 0; off >>= 1) {
        if (tid < off) red[tid] += red[tid + off];
        __syncthreads();
    }
    if (tid == 0) s_rk = rsqrtf(red[0] * (1.f / DIM) + 1e-6f);
    __syncthreads();

    const float rq = s_rq, rk = s_rk;

    const int hdim = grid_sizes[1];
    const int wdim = grid_sizes[2];
    const int wi = s % wdim;
    const int hi = (s / wdim) % hdim;
    const int fi = s / (wdim * hdim);

    for (int p = tid; p < NH * CHALF; p += 256) {
        const int head = p >> 6;
        const int c    = p & 63;
        int pos = (c < SEG0) ? fi : ((c < SEG0 + SEG1) ? hi : wi);
        float ang = freqs[(size_t)pos * CHALF + c];
        float sn, cs;
        sincosf(ang, &sn, &cs);

        const int d0 = head * HD + 2 * c;
        float q0 = qrow[d0]     * rq * gq[d0];
        float q1 = qrow[d0 + 1] * rq * gq[d0 + 1];
        float qv0 = q0 * cs - q1 * sn;
        float qv1 = q0 * sn + q1 * cs;

        float k0 = krow[d0]     * rk * gk[d0];
        float k1 = krow[d0 + 1] * rk * gk[d0 + 1];
        float kv0 = k0 * cs - k1 * sn;
        float kv1 = k0 * sn + k1 * cs;

        size_t i32 = ((size_t)s * DIM + d0) >> 1;
        uint32_t h, l;
        split2h(qv0, qv1, h, l);
        Qh[i32] = h; Ql[i32] = l;
        K16[i32] = pack2h(kv0, kv1);
    }
}

// ---------------- flash attention: fp16, single K/V, 4-slot ring ---------------
#define FQT    128
#define FKT    64
#define FPITCH 272
#define QH_OFF 0
#define QL_OFF (128 * FPITCH)           // 34816
#define RING_OFF (2 * 128 * FPITCH)     // 69632
#define K_O    0
#define V_O    (64 * FPITCH)            // 17408
#define SLOT_SZ (2 * 64 * FPITCH)       // 34816
#define FL_SMEM (RING_OFF + 4 * SLOT_SZ)  // 208896

__global__ __launch_bounds__(256, 1)
void flash_mma(const uint4* __restrict__ Qh, const uint4* __restrict__ Ql,
               const uint4* __restrict__ K16, const uint4* __restrict__ V16,
               uint32_t* __restrict__ AOh, uint32_t* __restrict__ AOl,
               const int* __restrict__ seq_lens, float qscale)
{
    extern __shared__ char smc[];
    const uint32_t sb = smem_u32(smc);
    const int tid  = threadIdx.x;
    const int wid  = tid >> 5;
    const int lane = tid & 31;
    const int g    = lane >> 2;
    const int t4   = lane & 3;
    const int head = blockIdx.y;
    const int q0   = blockIdx.x * FQT;
    const int seqlen = seq_lens[0];

    const int DIM8 = DIM / 8;
    const int h8   = head * (HD / 8);

    // stage Q hi/lo
#pragma unroll
    for (int i = 0; i < 8; i++) {
        int t = tid + 256 * i;
        int r = t >> 4, j = t & 15;
        uint32_t so = (uint32_t)(r * FPITCH + j * 16);
        size_t gi = (size_t)(q0 + r) * DIM8 + h8 + j;
        cp16(sb + QH_OFF + so, Qh + gi);
        cp16(sb + QL_OFF + so, Ql + gi);
    }
    CP_COMMIT();

    auto load_kv = [&](int kt, int slot) {
        uint32_t st = sb + RING_OFF + slot * SLOT_SZ;
        int kr0 = kt * FKT;
#pragma unroll
        for (int i = 0; i < 4; i++) {
            int t = tid + 256 * i;
            int r = t >> 4, j = t & 15;
            uint32_t so = (uint32_t)(r * FPITCH + j * 16);
            size_t gi = (size_t)(kr0 + r) * DIM8 + h8 + j;
            cp16(st + K_O + so, K16 + gi);
            cp16(st + V_O + so, V16 + gi);
        }
        CP_COMMIT();
    };

    load_kv(0, 0);
    load_kv(1, 1);
    load_kv(2, 2);

    const uint32_t a_off  = (uint32_t)((wid * 16 + (lane & 15)) * FPITCH + (lane >> 4) * 16);
    const uint32_t bk_off = (uint32_t)(((lane & 7) + ((lane >> 4) << 3)) * FPITCH
                                       + ((lane >> 3) & 1) * 16);
    const uint32_t bv_row = (uint32_t)((lane & 7) + (((lane >> 3) & 1) << 3));
    const uint32_t bv_col = (uint32_t)((lane >> 4) * 16);

    // Q fragments to registers (Q region stays private; no reuse)
    CP_WAIT(3);
    __syncthreads();
    uint32_t qhf[8][4], qlf[8][4];
#pragma unroll
    for (int kk = 0; kk < 8; kk++) {
        ldsm_x4(qhf[kk], sb + QH_OFF + a_off + kk * 32);
        ldsm_x4(qlf[kk], sb + QL_OFF + a_off + kk * 32);
    }

    float o[16][4];
#pragma unroll
    for (int i = 0; i < 16; i++)
#pragma unroll
        for (int j = 0; j < 4; j++) o[i][j] = 0.f;
    float m0 = -1e30f, m1 = -1e30f, l0 = 0.f, l1 = 0.f;

    const int NT = S_LEN / FKT;     // 32
    for (int kt = 0; kt < NT; kt++) {
        if (kt < NT - 2)      { CP_WAIT(2); }
        else if (kt == NT - 2){ CP_WAIT(1); }
        else                  { CP_WAIT(0); }
        __syncthreads();
        // slot (kt+3)&3 was last read at stage kt-1; barrier above freed it
        if (kt + 3 < NT) load_kv(kt + 3, (kt + 3) & 3);

        const uint32_t st = sb + RING_OFF + (kt & 3) * SLOT_SZ;

        // ---- scores: 2-term (qh + ql) x K16 ----
        float acc[8][4];
#pragma unroll
        for (int i = 0; i < 8; i++)
#pragma unroll
            for (int j = 0; j < 4; j++) acc[i][j] = 0.f;

#pragma unroll
        for (int kk = 0; kk < 8; kk++) {
#pragma unroll
            for (int np = 0; np < 4; np++) {
                uint32_t bh[4];
                ldsm_x4(bh, st + K_O + np * (16 * FPITCH) + bk_off + kk * 32);
                mma_f16(acc[2*np],   qhf[kk], &bh[0]);
                mma_f16(acc[2*np+1], qhf[kk], &bh[2]);
                mma_f16(acc[2*np],   qlf[kk], &bh[0]);
                mma_f16(acc[2*np+1], qlf[kk], &bh[2]);
            }
        }

        // ---- scale + mask + online softmax ----
        const int kr0 = kt * FKT;
        float mx0 = -1e30f, mx1 = -1e30f;
#pragma unroll
        for (int j = 0; j < 8; j++) {
#pragma unroll
            for (int i = 0; i < 4; i++) acc[j][i] *= qscale;
            int c0 = kr0 + 8 * j + 2 * t4;
            if (c0 >= seqlen)     { acc[j][0] = -1e30f; acc[j][2] = -1e30f; }
            if (c0 + 1 >= seqlen) { acc[j][1] = -1e30f; acc[j][3] = -1e30f; }
            mx0 = fmaxf(mx0, fmaxf(acc[j][0], acc[j][1]));
            mx1 = fmaxf(mx1, fmaxf(acc[j][2], acc[j][3]));
        }
        mx0 = fmaxf(mx0, __shfl_xor_sync(0xffffffffu, mx0, 1));
        mx0 = fmaxf(mx0, __shfl_xor_sync(0xffffffffu, mx0, 2));
        mx1 = fmaxf(mx1, __shfl_xor_sync(0xffffffffu, mx1, 1));
        mx1 = fmaxf(mx1, __shfl_xor_sync(0xffffffffu, mx1, 2));

        float mn0 = fmaxf(m0, mx0), mn1 = fmaxf(m1, mx1);
        float al0 = __expf(m0 - mn0), al1 = __expf(m1 - mn1);
        m0 = mn0; m1 = mn1;

        float s0 = 0.f, s1 = 0.f;
        uint32_t ph0[8], ph1[8], pl0[8], pl1[8];
#pragma unroll
        for (int j = 0; j < 8; j++) {
            float p00 = __expf(acc[j][0] - mn0);
            float p01 = __expf(acc[j][1] - mn0);
            float p10 = __expf(acc[j][2] - mn1);
            float p11 = __expf(acc[j][3] - mn1);
            s0 += p00 + p01;
            s1 += p10 + p11;
            split2h(p00, p01, ph0[j], pl0[j]);
            split2h(p10, p11, ph1[j], pl1[j]);
        }
        s0 += __shfl_xor_sync(0xffffffffu, s0, 1);
        s0 += __shfl_xor_sync(0xffffffffu, s0, 2);
        s1 += __shfl_xor_sync(0xffffffffu, s1, 1);
        s1 += __shfl_xor_sync(0xffffffffu, s1, 2);
        l0 = l0 * al0 + s0;
        l1 = l1 * al1 + s1;

#pragma unroll
        for (int nt = 0; nt < 16; nt++) {
            o[nt][0] *= al0; o[nt][1] *= al0;
            o[nt][2] *= al1; o[nt][3] *= al1;
        }

        // ---- PV: 2-term (ph + pl) x V16 ----
#pragma unroll
        for (int k2 = 0; k2 < 4; k2++) {
            uint32_t aph[4] = { ph0[2*k2], ph1[2*k2], ph0[2*k2+1], ph1[2*k2+1] };
            uint32_t apl[4] = { pl0[2*k2], pl1[2*k2], pl0[2*k2+1], pl1[2*k2+1] };
            uint32_t vrow = st + V_O + (uint32_t)((k2 * 16 + bv_row) * FPITCH) + bv_col;
#pragma unroll
            for (int d = 0; d < 8; d++) {
                uint32_t bv[4];
                ldsm_x4_t(bv, vrow + d * 32);
                mma_f16(o[2*d],   aph, &bv[0]);
                mma_f16(o[2*d+1], aph, &bv[2]);
                mma_f16(o[2*d],   apl, &bv[0]);
                mma_f16(o[2*d+1], apl, &bv[2]);
            }
        }
    }

    // ---- epilogue: fp16 split of normalized output ----
    float i0 = 1.f / l0, i1 = 1.f / l1;
    const int row0 = q0 + wid * 16 + g;
#pragma unroll
    for (int nt = 0; nt < 16; nt++) {
        int col = head * HD + nt * 8 + 2 * t4;
        uint32_t h0, lo0, h1, lo1;
        split2h(o[nt][0] * i0, o[nt][1] * i0, h0, lo0);
        split2h(o[nt][2] * i1, o[nt][3] * i1, h1, lo1);
        size_t i32a = ((size_t)row0 * DIM + col) >> 1;
        size_t i32b = ((size_t)(row0 + 8) * DIM + col) >> 1;
        AOh[i32a] = h0; AOl[i32a] = lo0;
        AOh[i32b] = h1; AOl[i32b] = lo1;
    }
}

// ---------------- launcher ---------------------------------------------------
extern "C" void kernel_launch(void* const* d_in, const int* in_sizes, int n_in,
                              void* d_out, int out_size)
{
    const float* x     = (const float*)d_in[0];
    const float* freqs = (const float*)d_in[1];
    const float* wq    = (const float*)d_in[2];
    const float* bq    = (const float*)d_in[3];
    const float* wk    = (const float*)d_in[4];
    const float* bk    = (const float*)d_in[5];
    const float* wv    = (const float*)d_in[6];
    const float* bv    = (const float*)d_in[7];
    const float* wo    = (const float*)d_in[8];
    const float* bo    = (const float*)d_in[9];
    const float* gq    = (const float*)d_in[10];
    const float* gk    = (const float*)d_in[11];
    const int*   seq_lens   = (const int*)d_in[12];
    const int*   grid_sizes = (const int*)d_in[13];
    float* out = (float*)d_out;

    float *q, *k;
    uint4 *xh, *xl, *w16, *wo16, *qh, *ql, *k16, *v16, *aoh, *aol;
    cudaGetSymbolAddress((void**)&q,    g_q);
    cudaGetSymbolAddress((void**)&k,    g_k);
    cudaGetSymbolAddress((void**)&xh,   g_xh);
    cudaGetSymbolAddress((void**)&xl,   g_xl);
    cudaGetSymbolAddress((void**)&w16,  g_w16);
    cudaGetSymbolAddress((void**)&wo16, g_wo16);
    cudaGetSymbolAddress((void**)&qh,   g_qh);
    cudaGetSymbolAddress((void**)&ql,   g_ql);
    cudaGetSymbolAddress((void**)&k16,  g_k16);
    cudaGetSymbolAddress((void**)&v16,  g_v16);
    cudaGetSymbolAddress((void**)&aoh,  g_aoh);
    cudaGetSymbolAddress((void**)&aol,  g_aol);

    const int n8x = S_LEN * DIM / 8;
    const int n8w = DIM * DIM / 8;
    const float qscale = 1.0f / sqrtf((float)HD);

    conv_split_h2<<<(n8x + 255) / 256, 256>>>((const float4*)x, xh, xl, n8x);
    conv_h1_w3<<<dim3((n8w + 255) / 256, 3), 256>>>(
        (const float4*)wq, (const float4*)wk, (const float4*)wv, w16, n8w);
    conv_h1<<<(n8w + 255) / 256, 256>>>((const float4*)wo, wo16, n8w);

    cudaFuncSetAttribute(gemm_mma, cudaFuncAttributeMaxDynamicSharedMemorySize, GEMM_SMEM);

    // fused QKV (V written as single fp16 directly)
    gemm_mma<<<dim3(S_LEN / 128, 36), 256, GEMM_SMEM>>>(
        xh, xl, w16, bq, bk, bv, q, k, (uint32_t*)v16, DIM / 128);

    norm_rope_split<<<S_LEN, 256>>>(q, k, gq, gk, freqs, grid_sizes,
                                    (uint32_t*)qh, (uint32_t*)ql, (uint32_t*)k16);

    cudaFuncSetAttribute(flash_mma, cudaFuncAttributeMaxDynamicSharedMemorySize, FL_SMEM);
    flash_mma<<<dim3(S_LEN / FQT, NH), 256, FL_SMEM>>>(
        qh, ql, k16, v16, (uint32_t*)aoh, (uint32_t*)aol, seq_lens, qscale);

    // output projection
    gemm_mma<<<dim3(S_LEN / 128, 12), 256, GEMM_SMEM>>>(
        aoh, aol, wo16, bo, bo, bo, out, out, (uint32_t*)v16, DIM / 128);
}